// round 6
// baseline (speedup 1.0000x reference)
#include <cuda_runtime.h>
#include <cuda_bf16.h>
#include <math.h>

#define ND   128
#define H1D  64
#define H2D  128
#define NG   64
#define MAXN 50000
#define MAXE 1600000
#define MAXET (MAXE + MAXN)
#define NEG_SLOPE 0.2f
#define NBLK 64

// ---------------- scratch ----------------
__device__ __align__(16) __nv_bfloat16 d_h1b[MAXN * H1D];
__device__ __align__(16) float d_y1[MAXN * H1D];
__device__ __align__(16) __nv_bfloat16 d_h2b[MAXN * H2D];
__device__ float d_as[MAXN];
__device__ float d_ad[MAXN];
__device__ float d_e[MAXET];
__device__ int   d_deg[MAXN];
__device__ int   d_cur[MAXN];
__device__ int   d_row[MAXN + 1];
__device__ int   d_csrc[MAXET];
__device__ int   d_bsum[NBLK];
__device__ __align__(16) float d_pool[NG * H2D];
__device__ float d_cnt[NG];
__device__ int   d_flag_e64;
__device__ int   d_flag_b64;

// ---------------- helpers ----------------
__device__ __forceinline__ void red_add4(float* p, float a, float b, float c, float d) {
    asm volatile("red.global.add.v4.f32 [%0], {%1,%2,%3,%4};"
                 :: "l"(p), "f"(a), "f"(b), "f"(c), "f"(d) : "memory");
}

__device__ __forceinline__ void load_edge(const void* ei, int i, int E, int is64, int& s, int& d) {
    if (is64) {
        const long long* p = (const long long*)ei;
        s = (int)p[i];
        d = (int)p[E + i];
    } else {
        const int* p = (const int*)ei;
        s = p[i];
        d = p[E + i];
    }
}

__device__ __forceinline__ int load_dst(const void* ei, int i, int E, int is64) {
    if (is64) return (int)((const long long*)ei)[E + i];
    return ((const int*)ei)[E + i];
}

// ---------------- dtype detection ----------------
__global__ void detect_kernel(const void* ei, const void* batch, int E, int N) {
    __shared__ int se, sb;
    int t = threadIdx.x;
    if (t == 0) { se = 1; sb = 1; }
    __syncthreads();
    if (t < 64) {
        long long v = ((const long long*)ei)[t];
        if (v < 0 || v >= (long long)N) atomicAnd(&se, 0);
    } else {
        int base = N / 2 - 64;
        long long v = ((const long long*)batch)[base + (t - 64)];
        if (v < 0 || v >= NG) atomicAnd(&sb, 0);
    }
    __syncthreads();
    if (t == 0) { d_flag_e64 = se; d_flag_b64 = sb; }
}

// ---------------- CSR build ----------------
// hist: 4 edges per thread (grid-stride style for MLP + coalescing)
__global__ void hist_kernel(const void* ei, int E, int T) {
    int i = blockIdx.x * blockDim.x + threadIdx.x;
    if (i >= T) return;
    int is64 = d_flag_e64;
    int j0 = i, j1 = i + T, j2 = i + 2 * T, j3 = i + 3 * T;
    if (j3 < E) {
        int d0 = load_dst(ei, j0, E, is64);
        int d1 = load_dst(ei, j1, E, is64);
        int d2 = load_dst(ei, j2, E, is64);
        int d3 = load_dst(ei, j3, E, is64);
        atomicAdd(&d_deg[d0], 1);
        atomicAdd(&d_deg[d1], 1);
        atomicAdd(&d_deg[d2], 1);
        atomicAdd(&d_deg[d3], 1);
    } else {
        for (int j = j0; j < E; j += T)
            atomicAdd(&d_deg[load_dst(ei, j, E, is64)], 1);
    }
}

__global__ void block_reduce_kernel(int N) {
    __shared__ int sm[256];
    int b = blockIdx.x, t = threadIdx.x;
    int base = b * 1024 + t * 4;
    int s = 0;
    #pragma unroll
    for (int k = 0; k < 4; k++) { int i = base + k; if (i < N) s += d_deg[i]; }
    sm[t] = s;
    __syncthreads();
    for (int off = 128; off; off >>= 1) {
        if (t < off) sm[t] += sm[t + off];
        __syncthreads();
    }
    if (t == 0) d_bsum[b] = sm[0];
}

// fused: scan of block sums + per-block scan + self-loop placement + cur init
__global__ void scan_fuse_kernel(int B, int N) {
    __shared__ int bsm[NBLK];
    __shared__ int sm[256];
    int b = blockIdx.x, t = threadIdx.x;
    if (t < NBLK) bsm[t] = (t < B) ? d_bsum[t] : 0;
    __syncthreads();
    int blkpre = 0, total = 0;
    for (int k = 0; k < B; k++) {
        int v = bsm[k];
        if (k < b) blkpre += v;
        total += v;
    }
    int base = b * 1024 + t * 4;
    int v[4], pre[4];
    int s = 0;
    #pragma unroll
    for (int k = 0; k < 4; k++) {
        int i = base + k;
        v[k] = (i < N) ? d_deg[i] : 0;
        pre[k] = s;
        s += v[k];
    }
    sm[t] = s;
    __syncthreads();
    for (int off = 1; off < 256; off <<= 1) {
        int u = (t >= off) ? sm[t - off] : 0;
        __syncthreads();
        sm[t] += u;
        __syncthreads();
    }
    int prefix = blkpre + (sm[t] - s);
    #pragma unroll
    for (int k = 0; k < 4; k++) {
        int i = base + k;
        if (i < N) {
            int r = prefix + pre[k] + i;   // +i self loops before i
            d_row[i] = r;
            d_csrc[r] = i;                 // self loop first
            d_cur[i] = r + 1;
        }
    }
    if (b == 0 && t == 0) d_row[N] = total + N;
}

// scatter: 2 edges per thread
__global__ void scatter_kernel(const void* ei, int E, int T) {
    int i = blockIdx.x * blockDim.x + threadIdx.x;
    if (i >= T) return;
    int is64 = d_flag_e64;
    int j0 = i, j1 = i + T;
    if (j1 < E) {
        int s0, d0, s1, d1;
        load_edge(ei, j0, E, is64, s0, d0);
        load_edge(ei, j1, E, is64, s1, d1);
        int p0 = atomicAdd(&d_cur[d0], 1);
        int p1 = atomicAdd(&d_cur[d1], 1);
        d_csrc[p0] = s0;
        d_csrc[p1] = s1;
    } else if (j0 < E) {
        int s0, d0;
        load_edge(ei, j0, E, is64, s0, d0);
        d_csrc[atomicAdd(&d_cur[d0], 1)] = s0;
    }
}

// ---------------- tiled GEMM with fused alphas, bf16 out, row-range --------
template <int K, int OUT>
__global__ void gemm_tiled(const float* __restrict__ A, const float* __restrict__ W,
                           __nv_bfloat16* __restrict__ Cb,
                           const float* __restrict__ avs, const float* __restrict__ avd,
                           int rowbase, int rowend) {
    const int CPT = OUT / 16;
    __shared__ float As[64][33];
    __shared__ float Ws[32][OUT];
    float acc[4][CPT];
    #pragma unroll
    for (int i = 0; i < 4; i++)
        #pragma unroll
        for (int j = 0; j < CPT; j++) acc[i][j] = 0.0f;

    int tx = threadIdx.x % 16, ty = threadIdx.x / 16;
    int row0 = rowbase + blockIdx.x * 64;

    for (int kk = 0; kk < K; kk += 32) {
        for (int i = threadIdx.x; i < 64 * 32; i += 256) {
            int r = i / 32, c = i % 32;
            int gr = row0 + r;
            As[r][c] = (gr < rowend) ? A[(size_t)gr * K + kk + c] : 0.0f;
        }
        for (int i = threadIdx.x; i < 32 * OUT; i += 256) {
            int r = i / OUT, c = i % OUT;
            Ws[r][c] = W[(size_t)(kk + r) * OUT + c];
        }
        __syncthreads();
        #pragma unroll
        for (int k = 0; k < 32; k++) {
            float a[4], w[CPT];
            #pragma unroll
            for (int i = 0; i < 4; i++) a[i] = As[ty * 4 + i][k];
            #pragma unroll
            for (int j = 0; j < CPT; j++) w[j] = Ws[k][j * 16 + tx];
            #pragma unroll
            for (int i = 0; i < 4; i++)
                #pragma unroll
                for (int j = 0; j < CPT; j++) acc[i][j] += a[i] * w[j];
        }
        __syncthreads();
    }

    #pragma unroll
    for (int i = 0; i < 4; i++) {
        int r = row0 + ty * 4 + i;
        if (r >= rowend) break;
        #pragma unroll
        for (int j = 0; j < CPT; j++)
            Cb[(size_t)r * OUT + j * 16 + tx] = __float2bfloat16(acc[i][j]);
    }

    float vs[CPT], vd[CPT];
    #pragma unroll
    for (int j = 0; j < CPT; j++) {
        vs[j] = avs[j * 16 + tx];
        vd[j] = avd[j * 16 + tx];
    }
    #pragma unroll
    for (int i = 0; i < 4; i++) {
        float ps = 0.0f, pd = 0.0f;
        #pragma unroll
        for (int j = 0; j < CPT; j++) {
            ps += acc[i][j] * vs[j];
            pd += acc[i][j] * vd[j];
        }
        #pragma unroll
        for (int o = 8; o; o >>= 1) {
            ps += __shfl_xor_sync(0xFFFFFFFFu, ps, o);
            pd += __shfl_xor_sync(0xFFFFFFFFu, pd, o);
        }
        int r = row0 + ty * 4 + i;
        if (tx == 0 && r < rowend) { d_as[r] = ps; d_ad[r] = pd; }
    }
}

// ---------------- online softmax prologue (single edge pass) ----------------
// computes e per edge, stores raw e in d_e, returns (m, inv)
__device__ __forceinline__ void gat_softmax_online(int beg, int end, int lane, float ad_d,
                                                   float& m_out, float& inv_out) {
    float m = -1e30f, den = 0.0f;
    for (int j = beg + lane; j < end; j += 32) {
        int s = d_csrc[j];
        float e = d_as[s] + ad_d;
        e = (e > 0.0f) ? e : NEG_SLOPE * e;
        d_e[j] = e;
        if (e > m) { den = den * __expf(m - e) + 1.0f; m = e; }
        else       { den += __expf(e - m); }
    }
    #pragma unroll
    for (int o = 16; o; o >>= 1) {
        float mo = __shfl_xor_sync(0xFFFFFFFFu, m, o);
        float dn = __shfl_xor_sync(0xFFFFFFFFu, den, o);
        float nm = fmaxf(m, mo);
        den = den * __expf(m - nm) + dn * __expf(mo - nm);
        m = nm;
    }
    m_out = m;
    inv_out = 1.0f / (den + 1e-16f);
}

__device__ __forceinline__ void bf16x2u(unsigned u, float& f0, float& f1) {
    f0 = __uint_as_float(u << 16);
    f1 = __uint_as_float(u & 0xFFFF0000u);
}
__device__ __forceinline__ void bf16x4(uint2 u, float& f0, float& f1, float& f2, float& f3) {
    f0 = __uint_as_float(u.x << 16);
    f1 = __uint_as_float(u.x & 0xFFFF0000u);
    f2 = __uint_as_float(u.y << 16);
    f3 = __uint_as_float(u.y & 0xFFFF0000u);
}

// ---------------- layer-1: nodes [n0, n1) -----------------------------------
__global__ void gat1_kernel(const __nv_bfloat16* __restrict__ h, const float* __restrict__ bias,
                            float* __restrict__ y, int n0, int n1) {
    int w = n0 + ((blockIdx.x * blockDim.x + threadIdx.x) >> 5);
    int lane = threadIdx.x & 31;
    if (w >= n1) return;
    int beg = d_row[w], end = d_row[w + 1];
    float m, inv;
    gat_softmax_online(beg, end, lane, d_ad[w], m, inv);

    float ax = 0.0f, ay = 0.0f;
    int j = beg;
    for (; j + 4 <= end; j += 4) {
        int s0 = d_csrc[j], s1 = d_csrc[j + 1], s2 = d_csrc[j + 2], s3 = d_csrc[j + 3];
        float a0 = __expf(d_e[j] - m);
        float a1 = __expf(d_e[j + 1] - m);
        float a2 = __expf(d_e[j + 2] - m);
        float a3 = __expf(d_e[j + 3] - m);
        unsigned u0 = *((const unsigned*)(h + (size_t)s0 * H1D) + lane);
        unsigned u1 = *((const unsigned*)(h + (size_t)s1 * H1D) + lane);
        unsigned u2 = *((const unsigned*)(h + (size_t)s2 * H1D) + lane);
        unsigned u3 = *((const unsigned*)(h + (size_t)s3 * H1D) + lane);
        float x0, x1;
        bf16x2u(u0, x0, x1); ax += a0 * x0; ay += a0 * x1;
        bf16x2u(u1, x0, x1); ax += a1 * x0; ay += a1 * x1;
        bf16x2u(u2, x0, x1); ax += a2 * x0; ay += a2 * x1;
        bf16x2u(u3, x0, x1); ax += a3 * x0; ay += a3 * x1;
    }
    for (; j < end; j++) {
        int s = d_csrc[j];
        float a = __expf(d_e[j] - m);
        unsigned u = *((const unsigned*)(h + (size_t)s * H1D) + lane);
        float x0, x1;
        bf16x2u(u, x0, x1); ax += a * x0; ay += a * x1;
    }
    const float2 bb = *(const float2*)(bias + lane * 2);
    float2 r;
    r.x = fmaxf(ax * inv + bb.x, 0.0f);
    r.y = fmaxf(ay * inv + bb.y, 0.0f);
    *(float2*)(y + (size_t)w * H1D + lane * 2) = r;
}

// ---------------- layer-2 + pool ---------------------------------------------
__global__ void gat2_kernel(const __nv_bfloat16* __restrict__ h, const float* __restrict__ bias,
                            const void* batch, int N) {
    int w = (blockIdx.x * blockDim.x + threadIdx.x) >> 5;
    int lane = threadIdx.x & 31;
    if (w >= N) return;
    int beg = d_row[w], end = d_row[w + 1];
    float m, inv;
    gat_softmax_online(beg, end, lane, d_ad[w], m, inv);

    float4 acc = make_float4(0.f, 0.f, 0.f, 0.f);
    int j = beg;
    for (; j + 4 <= end; j += 4) {
        int s0 = d_csrc[j], s1 = d_csrc[j + 1], s2 = d_csrc[j + 2], s3 = d_csrc[j + 3];
        float a0 = __expf(d_e[j] - m);
        float a1 = __expf(d_e[j + 1] - m);
        float a2 = __expf(d_e[j + 2] - m);
        float a3 = __expf(d_e[j + 3] - m);
        uint2 u0 = *((const uint2*)(h + (size_t)s0 * H2D) + lane);
        uint2 u1 = *((const uint2*)(h + (size_t)s1 * H2D) + lane);
        uint2 u2 = *((const uint2*)(h + (size_t)s2 * H2D) + lane);
        uint2 u3 = *((const uint2*)(h + (size_t)s3 * H2D) + lane);
        float x0, x1, x2, x3;
        bf16x4(u0, x0, x1, x2, x3);
        acc.x += a0 * x0; acc.y += a0 * x1; acc.z += a0 * x2; acc.w += a0 * x3;
        bf16x4(u1, x0, x1, x2, x3);
        acc.x += a1 * x0; acc.y += a1 * x1; acc.z += a1 * x2; acc.w += a1 * x3;
        bf16x4(u2, x0, x1, x2, x3);
        acc.x += a2 * x0; acc.y += a2 * x1; acc.z += a2 * x2; acc.w += a2 * x3;
        bf16x4(u3, x0, x1, x2, x3);
        acc.x += a3 * x0; acc.y += a3 * x1; acc.z += a3 * x2; acc.w += a3 * x3;
    }
    for (; j < end; j++) {
        int s = d_csrc[j];
        float a = __expf(d_e[j] - m);
        uint2 u = *((const uint2*)(h + (size_t)s * H2D) + lane);
        float x0, x1, x2, x3;
        bf16x4(u, x0, x1, x2, x3);
        acc.x += a * x0; acc.y += a * x1; acc.z += a * x2; acc.w += a * x3;
    }
    const float4 bb = *(const float4*)(bias + lane * 4);
    float r0 = fmaxf(acc.x * inv + bb.x, 0.0f);
    float r1 = fmaxf(acc.y * inv + bb.y, 0.0f);
    float r2 = fmaxf(acc.z * inv + bb.z, 0.0f);
    float r3 = fmaxf(acc.w * inv + bb.w, 0.0f);
    int b;
    if (d_flag_b64) b = (int)((const long long*)batch)[w];
    else            b = ((const int*)batch)[w];
    red_add4(d_pool + (size_t)b * H2D + lane * 4, r0, r1, r2, r3);
}

// ---------------- counts (warp-aggregated) ----------------
__global__ void counts_kernel(const void* batch, int N) {
    int n = blockIdx.x * blockDim.x + threadIdx.x;
    unsigned mask = __ballot_sync(0xFFFFFFFFu, n < N);
    if (n >= N) return;
    int b;
    if (d_flag_b64) b = (int)((const long long*)batch)[n];
    else            b = ((const int*)batch)[n];
    unsigned peers = __match_any_sync(mask, b);
    int leader = __ffs(peers) - 1;
    if ((threadIdx.x & 31) == leader)
        atomicAdd(&d_cnt[b], (float)__popc(peers));
}

__global__ void fc_kernel(const float* __restrict__ Wfc, const float* __restrict__ bfc,
                          float* __restrict__ out) {
    __shared__ float p[H2D];
    int g = blockIdx.x;
    int f = threadIdx.x;
    float cnt = fmaxf(d_cnt[g], 1.0f);
    for (int k = f; k < H2D; k += 64) p[k] = d_pool[g * H2D + k] / cnt;
    __syncthreads();
    float acc = bfc[f];
    #pragma unroll 16
    for (int k = 0; k < H2D; k++) acc += p[k] * Wfc[k * 64 + f];
    out[g * 64 + f] = acc;
}

// ---------------- launch ----------------
static inline int cdiv(long long a, int b) { return (int)((a + b - 1) / b); }

extern "C" void kernel_launch(void* const* d_in, const int* in_sizes, int n_in,
                              void* d_out, int out_size) {
    const float* x      = (const float*)d_in[0];
    const void*  ei     = d_in[1];
    const void*  batch  = d_in[2];
    const float* W1     = (const float*)d_in[3];
    const float* a_src1 = (const float*)d_in[4];
    const float* a_dst1 = (const float*)d_in[5];
    const float* b1     = (const float*)d_in[6];
    const float* W2     = (const float*)d_in[7];
    const float* a_src2 = (const float*)d_in[8];
    const float* a_dst2 = (const float*)d_in[9];
    const float* b2     = (const float*)d_in[10];
    const float* Wfc    = (const float*)d_in[11];
    const float* bfc    = (const float*)d_in[12];
    float* out = (float*)d_out;

    const int N = in_sizes[2];
    const int E = in_sizes[1] / 2;
    const int B = cdiv(N, 1024);
    const int Nh = ((N / 2 + 63) / 64) * 64;     // split point (multiple of 64)

    static cudaStream_t s2 = nullptr;
    static cudaEvent_t ev0 = nullptr, evA = nullptr, evG1A = nullptr, evG1B = nullptr, evA2 = nullptr;
    if (!s2) {
        if (cudaStreamCreateWithFlags(&s2, cudaStreamNonBlocking) != cudaSuccess) s2 = nullptr;
        cudaEventCreateWithFlags(&ev0, cudaEventDisableTiming);
        cudaEventCreateWithFlags(&evA, cudaEventDisableTiming);
        cudaEventCreateWithFlags(&evG1A, cudaEventDisableTiming);
        cudaEventCreateWithFlags(&evG1B, cudaEventDisableTiming);
        cudaEventCreateWithFlags(&evA2, cudaEventDisableTiming);
    }
    const bool fork = (s2 != nullptr);
    cudaStream_t sb = fork ? s2 : (cudaStream_t)0;

    void *ppool, *pcnt, *pdeg;
    cudaGetSymbolAddress(&ppool, d_pool);
    cudaGetSymbolAddress(&pcnt, d_cnt);
    cudaGetSymbolAddress(&pdeg, d_deg);
    cudaMemsetAsync(ppool, 0, NG * H2D * sizeof(float), 0);
    cudaMemsetAsync(pcnt, 0, NG * sizeof(float), 0);
    cudaMemsetAsync(pdeg, 0, (size_t)N * sizeof(int), 0);

    detect_kernel<<<1, 128, 0, 0>>>(ei, batch, E, N);

    __nv_bfloat16 *h1p, *h2p;
    float *y1p;
    cudaGetSymbolAddress((void**)&h1p, d_h1b);
    cudaGetSymbolAddress((void**)&y1p, d_y1);
    cudaGetSymbolAddress((void**)&h2p, d_h2b);

    // side stream: counts + GEMM1 while main builds CSR
    if (fork) {
        cudaEventRecord(ev0, 0);
        cudaStreamWaitEvent(sb, ev0, 0);
    }
    counts_kernel<<<cdiv(N, 256), 256, 0, sb>>>(batch, N);
    gemm_tiled<ND, H1D><<<cdiv(N, 64), 256, 0, sb>>>(x, W1, h1p, a_src1, a_dst1, 0, N);
    if (fork) cudaEventRecord(evA, sb);

    // main: CSR build
    const int Th = cdiv(E, 4);
    const int Ts = cdiv(E, 2);
    hist_kernel<<<cdiv(Th, 256), 256, 0, 0>>>(ei, E, Th);
    block_reduce_kernel<<<B, 256, 0, 0>>>(N);
    scan_fuse_kernel<<<B, 256, 0, 0>>>(B, N);
    scatter_kernel<<<cdiv(Ts, 256), 256, 0, 0>>>(ei, E, Ts);

    if (fork) cudaStreamWaitEvent(0, evA, 0);

    // layer 1 split-half, pipelined with gemm2 halves on the side stream
    gat1_kernel<<<cdiv(Nh, 8), 256, 0, 0>>>(h1p, b1, y1p, 0, Nh);
    if (fork) {
        cudaEventRecord(evG1A, 0);
        cudaStreamWaitEvent(sb, evG1A, 0);
    }
    gat1_kernel<<<cdiv(N - Nh, 8), 256, 0, 0>>>(h1p, b1, y1p, Nh, N);
    if (fork) {
        cudaEventRecord(evG1B, 0);
        gemm_tiled<H1D, H2D><<<cdiv(Nh, 64), 256, 0, sb>>>(y1p, W2, h2p, a_src2, a_dst2, 0, Nh);
        cudaStreamWaitEvent(sb, evG1B, 0);
        gemm_tiled<H1D, H2D><<<cdiv(N - Nh, 64), 256, 0, sb>>>(y1p, W2, h2p, a_src2, a_dst2, Nh, N);
        cudaEventRecord(evA2, sb);
        cudaStreamWaitEvent(0, evA2, 0);
    } else {
        gemm_tiled<H1D, H2D><<<cdiv(Nh, 64), 256, 0, 0>>>(y1p, W2, h2p, a_src2, a_dst2, 0, Nh);
        gemm_tiled<H1D, H2D><<<cdiv(N - Nh, 64), 256, 0, 0>>>(y1p, W2, h2p, a_src2, a_dst2, Nh, N);
    }

    gat2_kernel<<<cdiv(N, 8), 256, 0, 0>>>(h2p, b2, batch, N);
    fc_kernel<<<NG, 64, 0, 0>>>(Wfc, bfc, out);
}

// round 9
// speedup vs baseline: 1.0934x; 1.0934x over previous
#include <cuda_runtime.h>
#include <cuda_bf16.h>
#include <math.h>

#define ND   128
#define H1D  64
#define H2D  128
#define NG   64
#define MAXN 50000
#define MAXE 1600000
#define MAXET (MAXE + MAXN)
#define NEG_SLOPE 0.2f
#define NBLK 64

// ---------------- scratch ----------------
__device__ __align__(16) __nv_bfloat16 d_h1b[MAXN * H1D];
__device__ __align__(16) float d_y1[MAXN * H1D];
__device__ __align__(16) __nv_bfloat16 d_h2b[MAXN * H2D];
__device__ float d_as[MAXN];
__device__ float d_ad[MAXN];
__device__ float d_e[MAXET];
__device__ int   d_deg[MAXN];
__device__ int   d_cur[MAXN];
__device__ int   d_row[MAXN + 1];
__device__ int   d_csrc[MAXET];
__device__ int   d_bsum[NBLK];
__device__ __align__(16) float d_pool[NG * H2D];
__device__ float d_cnt[NG];
__device__ int   d_flag_e64;
__device__ int   d_flag_b64;

// ---------------- helpers ----------------
__device__ __forceinline__ void red_add4(float* p, float a, float b, float c, float d) {
    asm volatile("red.global.add.v4.f32 [%0], {%1,%2,%3,%4};"
                 :: "l"(p), "f"(a), "f"(b), "f"(c), "f"(d) : "memory");
}

__device__ __forceinline__ void load_edge(const void* ei, int i, int E, int is64, int& s, int& d) {
    if (is64) {
        const long long* p = (const long long*)ei;
        s = (int)p[i];
        d = (int)p[E + i];
    } else {
        const int* p = (const int*)ei;
        s = p[i];
        d = p[E + i];
    }
}

__device__ __forceinline__ int load_dst(const void* ei, int i, int E, int is64) {
    if (is64) return (int)((const long long*)ei)[E + i];
    return ((const int*)ei)[E + i];
}

// ---------------- dtype detection ----------------
__global__ void detect_kernel(const void* ei, const void* batch, int E, int N) {
    __shared__ int se, sb;
    int t = threadIdx.x;
    if (t == 0) { se = 1; sb = 1; }
    __syncthreads();
    if (t < 64) {
        long long v = ((const long long*)ei)[t];
        if (v < 0 || v >= (long long)N) atomicAnd(&se, 0);
    } else {
        int base = N / 2 - 64;
        long long v = ((const long long*)batch)[base + (t - 64)];
        if (v < 0 || v >= NG) atomicAnd(&sb, 0);
    }
    __syncthreads();
    if (t == 0) { d_flag_e64 = se; d_flag_b64 = sb; }
}

// ---------------- CSR build ----------------
__global__ void hist_kernel(const void* ei, int E) {
    int i = blockIdx.x * blockDim.x + threadIdx.x;
    if (i >= E) return;
    int d = load_dst(ei, i, E, d_flag_e64);
    atomicAdd(&d_deg[d], 1);
}

__global__ void block_reduce_kernel(int N) {
    __shared__ int sm[256];
    int b = blockIdx.x, t = threadIdx.x;
    int base = b * 1024 + t * 4;
    int s = 0;
    #pragma unroll
    for (int k = 0; k < 4; k++) { int i = base + k; if (i < N) s += d_deg[i]; }
    sm[t] = s;
    __syncthreads();
    for (int off = 128; off; off >>= 1) {
        if (t < off) sm[t] += sm[t + off];
        __syncthreads();
    }
    if (t == 0) d_bsum[b] = sm[0];
}

// fused: scan of block sums + per-block scan + self-loop placement + cur init
__global__ void scan_fuse_kernel(int B, int N) {
    __shared__ int bsm[NBLK];
    __shared__ int sm[256];
    int b = blockIdx.x, t = threadIdx.x;
    if (t < NBLK) bsm[t] = (t < B) ? d_bsum[t] : 0;
    __syncthreads();
    int blkpre = 0, total = 0;
    for (int k = 0; k < B; k++) {
        int v = bsm[k];
        if (k < b) blkpre += v;
        total += v;
    }
    int base = b * 1024 + t * 4;
    int v[4], pre[4];
    int s = 0;
    #pragma unroll
    for (int k = 0; k < 4; k++) {
        int i = base + k;
        v[k] = (i < N) ? d_deg[i] : 0;
        pre[k] = s;
        s += v[k];
    }
    sm[t] = s;
    __syncthreads();
    for (int off = 1; off < 256; off <<= 1) {
        int u = (t >= off) ? sm[t - off] : 0;
        __syncthreads();
        sm[t] += u;
        __syncthreads();
    }
    int prefix = blkpre + (sm[t] - s);
    #pragma unroll
    for (int k = 0; k < 4; k++) {
        int i = base + k;
        if (i < N) {
            int r = prefix + pre[k] + i;   // +i self loops before i
            d_row[i] = r;
            d_csrc[r] = i;                 // self loop first
            d_cur[i] = r + 1;
        }
    }
    if (b == 0 && t == 0) d_row[N] = total + N;
}

__global__ void scatter_kernel(const void* ei, int E) {
    int i = blockIdx.x * blockDim.x + threadIdx.x;
    if (i >= E) return;
    int is64 = d_flag_e64;
    int s, d;
    load_edge(ei, i, E, is64, s, d);
    int p = atomicAdd(&d_cur[d], 1);
    d_csrc[p] = s;
}

// ---------------- tiled GEMM with fused alphas, bf16 out --------------------
template <int K, int OUT>
__global__ void gemm_tiled(const float* __restrict__ A, const float* __restrict__ W,
                           __nv_bfloat16* __restrict__ Cb,
                           const float* __restrict__ avs, const float* __restrict__ avd,
                           int N) {
    const int CPT = OUT / 16;
    __shared__ float As[64][33];
    __shared__ float Ws[32][OUT];
    float acc[4][CPT];
    #pragma unroll
    for (int i = 0; i < 4; i++)
        #pragma unroll
        for (int j = 0; j < CPT; j++) acc[i][j] = 0.0f;

    int tx = threadIdx.x % 16, ty = threadIdx.x / 16;
    int row0 = blockIdx.x * 64;

    for (int kk = 0; kk < K; kk += 32) {
        for (int i = threadIdx.x; i < 64 * 32; i += 256) {
            int r = i / 32, c = i % 32;
            int gr = row0 + r;
            As[r][c] = (gr < N) ? A[(size_t)gr * K + kk + c] : 0.0f;
        }
        for (int i = threadIdx.x; i < 32 * OUT; i += 256) {
            int r = i / OUT, c = i % OUT;
            Ws[r][c] = W[(size_t)(kk + r) * OUT + c];
        }
        __syncthreads();
        #pragma unroll
        for (int k = 0; k < 32; k++) {
            float a[4], w[CPT];
            #pragma unroll
            for (int i = 0; i < 4; i++) a[i] = As[ty * 4 + i][k];
            #pragma unroll
            for (int j = 0; j < CPT; j++) w[j] = Ws[k][j * 16 + tx];
            #pragma unroll
            for (int i = 0; i < 4; i++)
                #pragma unroll
                for (int j = 0; j < CPT; j++) acc[i][j] += a[i] * w[j];
        }
        __syncthreads();
    }

    #pragma unroll
    for (int i = 0; i < 4; i++) {
        int r = row0 + ty * 4 + i;
        if (r >= N) break;
        #pragma unroll
        for (int j = 0; j < CPT; j++)
            Cb[(size_t)r * OUT + j * 16 + tx] = __float2bfloat16(acc[i][j]);
    }

    float vs[CPT], vd[CPT];
    #pragma unroll
    for (int j = 0; j < CPT; j++) {
        vs[j] = avs[j * 16 + tx];
        vd[j] = avd[j * 16 + tx];
    }
    #pragma unroll
    for (int i = 0; i < 4; i++) {
        float ps = 0.0f, pd = 0.0f;
        #pragma unroll
        for (int j = 0; j < CPT; j++) {
            ps += acc[i][j] * vs[j];
            pd += acc[i][j] * vd[j];
        }
        #pragma unroll
        for (int o = 8; o; o >>= 1) {
            ps += __shfl_xor_sync(0xFFFFFFFFu, ps, o);
            pd += __shfl_xor_sync(0xFFFFFFFFu, pd, o);
        }
        int r = row0 + ty * 4 + i;
        if (tx == 0 && r < N) { d_as[r] = ps; d_ad[r] = pd; }
    }
}

// ---------------- two-pass softmax: stores ex per edge, returns inv ---------
__device__ __forceinline__ float gat_softmax(int beg, int end, int lane, float ad_d) {
    float m = -INFINITY;
    for (int j = beg + lane; j < end; j += 32) {
        int s = d_csrc[j];
        float e = d_as[s] + ad_d;
        e = (e > 0.0f) ? e : NEG_SLOPE * e;
        d_e[j] = e;
        m = fmaxf(m, e);
    }
    #pragma unroll
    for (int o = 16; o; o >>= 1) m = fmaxf(m, __shfl_xor_sync(0xFFFFFFFFu, m, o));
    float den = 0.0f;
    for (int j = beg + lane; j < end; j += 32) {
        float ex = __expf(d_e[j] - m);
        d_e[j] = ex;
        den += ex;
    }
    #pragma unroll
    for (int o = 16; o; o >>= 1) den += __shfl_xor_sync(0xFFFFFFFFu, den, o);
    return 1.0f / (den + 1e-16f);
}

__device__ __forceinline__ void bf16x2u(unsigned u, float& f0, float& f1) {
    f0 = __uint_as_float(u << 16);
    f1 = __uint_as_float(u & 0xFFFF0000u);
}
__device__ __forceinline__ void bf16x4(uint2 u, float& f0, float& f1, float& f2, float& f3) {
    f0 = __uint_as_float(u.x << 16);
    f1 = __uint_as_float(u.x & 0xFFFF0000u);
    f2 = __uint_as_float(u.y << 16);
    f3 = __uint_as_float(u.y & 0xFFFF0000u);
}

// ---------------- layer-1 aggregation (bf16 gather, F=64) -------------------
__global__ void gat1_kernel(const __nv_bfloat16* __restrict__ h, const float* __restrict__ bias,
                            float* __restrict__ y, int N) {
    int w = (blockIdx.x * blockDim.x + threadIdx.x) >> 5;
    int lane = threadIdx.x & 31;
    if (w >= N) return;
    int beg = d_row[w], end = d_row[w + 1];
    float inv = gat_softmax(beg, end, lane, d_ad[w]);

    float ax = 0.0f, ay = 0.0f;
    int j = beg;
    for (; j + 4 <= end; j += 4) {
        int s0 = d_csrc[j], s1 = d_csrc[j + 1], s2 = d_csrc[j + 2], s3 = d_csrc[j + 3];
        float a0 = d_e[j] * inv, a1 = d_e[j + 1] * inv;
        float a2 = d_e[j + 2] * inv, a3 = d_e[j + 3] * inv;
        unsigned u0 = *((const unsigned*)(h + (size_t)s0 * H1D) + lane);
        unsigned u1 = *((const unsigned*)(h + (size_t)s1 * H1D) + lane);
        unsigned u2 = *((const unsigned*)(h + (size_t)s2 * H1D) + lane);
        unsigned u3 = *((const unsigned*)(h + (size_t)s3 * H1D) + lane);
        float x0, x1;
        bf16x2u(u0, x0, x1); ax += a0 * x0; ay += a0 * x1;
        bf16x2u(u1, x0, x1); ax += a1 * x0; ay += a1 * x1;
        bf16x2u(u2, x0, x1); ax += a2 * x0; ay += a2 * x1;
        bf16x2u(u3, x0, x1); ax += a3 * x0; ay += a3 * x1;
    }
    for (; j < end; j++) {
        int s = d_csrc[j];
        float a = d_e[j] * inv;
        unsigned u = *((const unsigned*)(h + (size_t)s * H1D) + lane);
        float x0, x1;
        bf16x2u(u, x0, x1); ax += a * x0; ay += a * x1;
    }
    const float2 bb = *(const float2*)(bias + lane * 2);
    float2 r;
    r.x = fmaxf(ax + bb.x, 0.0f);
    r.y = fmaxf(ay + bb.y, 0.0f);
    *(float2*)(y + (size_t)w * H1D + lane * 2) = r;
}

// ---------------- layer-2 aggregation + pool --------------------------------
__global__ void gat2_kernel(const __nv_bfloat16* __restrict__ h, const float* __restrict__ bias,
                            const void* batch, int N) {
    int w = (blockIdx.x * blockDim.x + threadIdx.x) >> 5;
    int lane = threadIdx.x & 31;
    if (w >= N) return;
    int beg = d_row[w], end = d_row[w + 1];
    float inv = gat_softmax(beg, end, lane, d_ad[w]);

    float4 acc = make_float4(0.f, 0.f, 0.f, 0.f);
    int j = beg;
    for (; j + 4 <= end; j += 4) {
        int s0 = d_csrc[j], s1 = d_csrc[j + 1], s2 = d_csrc[j + 2], s3 = d_csrc[j + 3];
        float a0 = d_e[j] * inv, a1 = d_e[j + 1] * inv;
        float a2 = d_e[j + 2] * inv, a3 = d_e[j + 3] * inv;
        uint2 u0 = *((const uint2*)(h + (size_t)s0 * H2D) + lane);
        uint2 u1 = *((const uint2*)(h + (size_t)s1 * H2D) + lane);
        uint2 u2 = *((const uint2*)(h + (size_t)s2 * H2D) + lane);
        uint2 u3 = *((const uint2*)(h + (size_t)s3 * H2D) + lane);
        float x0, x1, x2, x3;
        bf16x4(u0, x0, x1, x2, x3);
        acc.x += a0 * x0; acc.y += a0 * x1; acc.z += a0 * x2; acc.w += a0 * x3;
        bf16x4(u1, x0, x1, x2, x3);
        acc.x += a1 * x0; acc.y += a1 * x1; acc.z += a1 * x2; acc.w += a1 * x3;
        bf16x4(u2, x0, x1, x2, x3);
        acc.x += a2 * x0; acc.y += a2 * x1; acc.z += a2 * x2; acc.w += a2 * x3;
        bf16x4(u3, x0, x1, x2, x3);
        acc.x += a3 * x0; acc.y += a3 * x1; acc.z += a3 * x2; acc.w += a3 * x3;
    }
    for (; j < end; j++) {
        int s = d_csrc[j];
        float a = d_e[j] * inv;
        uint2 u = *((const uint2*)(h + (size_t)s * H2D) + lane);
        float x0, x1, x2, x3;
        bf16x4(u, x0, x1, x2, x3);
        acc.x += a * x0; acc.y += a * x1; acc.z += a * x2; acc.w += a * x3;
    }
    const float4 bb = *(const float4*)(bias + lane * 4);
    float r0 = fmaxf(acc.x + bb.x, 0.0f);
    float r1 = fmaxf(acc.y + bb.y, 0.0f);
    float r2 = fmaxf(acc.z + bb.z, 0.0f);
    float r3 = fmaxf(acc.w + bb.w, 0.0f);
    int b;
    if (d_flag_b64) b = (int)((const long long*)batch)[w];
    else            b = ((const int*)batch)[w];
    red_add4(d_pool + (size_t)b * H2D + lane * 4, r0, r1, r2, r3);
}

// ---------------- counts (warp-aggregated) ----------------
__global__ void counts_kernel(const void* batch, int N) {
    int n = blockIdx.x * blockDim.x + threadIdx.x;
    unsigned mask = __ballot_sync(0xFFFFFFFFu, n < N);
    if (n >= N) return;
    int b;
    if (d_flag_b64) b = (int)((const long long*)batch)[n];
    else            b = ((const int*)batch)[n];
    unsigned peers = __match_any_sync(mask, b);
    int leader = __ffs(peers) - 1;
    if ((threadIdx.x & 31) == leader)
        atomicAdd(&d_cnt[b], (float)__popc(peers));
}

__global__ void fc_kernel(const float* __restrict__ Wfc, const float* __restrict__ bfc,
                          float* __restrict__ out) {
    __shared__ float p[H2D];
    int g = blockIdx.x;
    int f = threadIdx.x;
    float cnt = fmaxf(d_cnt[g], 1.0f);
    for (int k = f; k < H2D; k += 64) p[k] = d_pool[g * H2D + k] / cnt;
    __syncthreads();
    float acc = bfc[f];
    #pragma unroll 16
    for (int k = 0; k < H2D; k++) acc += p[k] * Wfc[k * 64 + f];
    out[g * 64 + f] = acc;
}

// ---------------- launch ----------------
static inline int cdiv(long long a, int b) { return (int)((a + b - 1) / b); }

extern "C" void kernel_launch(void* const* d_in, const int* in_sizes, int n_in,
                              void* d_out, int out_size) {
    const float* x      = (const float*)d_in[0];
    const void*  ei     = d_in[1];
    const void*  batch  = d_in[2];
    const float* W1     = (const float*)d_in[3];
    const float* a_src1 = (const float*)d_in[4];
    const float* a_dst1 = (const float*)d_in[5];
    const float* b1     = (const float*)d_in[6];
    const float* W2     = (const float*)d_in[7];
    const float* a_src2 = (const float*)d_in[8];
    const float* a_dst2 = (const float*)d_in[9];
    const float* b2     = (const float*)d_in[10];
    const float* Wfc    = (const float*)d_in[11];
    const float* bfc    = (const float*)d_in[12];
    float* out = (float*)d_out;

    const int N = in_sizes[2];
    const int E = in_sizes[1] / 2;
    const int B = cdiv(N, 1024);

    static cudaStream_t s2 = nullptr;
    static cudaEvent_t ev0 = nullptr, evA = nullptr;
    if (!s2) {
        if (cudaStreamCreateWithFlags(&s2, cudaStreamNonBlocking) != cudaSuccess) s2 = nullptr;
        cudaEventCreateWithFlags(&ev0, cudaEventDisableTiming);
        cudaEventCreateWithFlags(&evA, cudaEventDisableTiming);
    }
    const bool fork = (s2 != nullptr);
    cudaStream_t sb = fork ? s2 : (cudaStream_t)0;

    void *ppool, *pcnt, *pdeg;
    cudaGetSymbolAddress(&ppool, d_pool);
    cudaGetSymbolAddress(&pcnt, d_cnt);
    cudaGetSymbolAddress(&pdeg, d_deg);
    cudaMemsetAsync(ppool, 0, NG * H2D * sizeof(float), 0);
    cudaMemsetAsync(pcnt, 0, NG * sizeof(float), 0);
    cudaMemsetAsync(pdeg, 0, (size_t)N * sizeof(int), 0);

    detect_kernel<<<1, 128, 0, 0>>>(ei, batch, E, N);

    __nv_bfloat16 *h1p, *h2p;
    float *y1p;
    cudaGetSymbolAddress((void**)&h1p, d_h1b);
    cudaGetSymbolAddress((void**)&y1p, d_y1);
    cudaGetSymbolAddress((void**)&h2p, d_h2b);

    // side stream: GEMM1 first (longest), then counts
    if (fork) {
        cudaEventRecord(ev0, 0);
        cudaStreamWaitEvent(sb, ev0, 0);
    }
    gemm_tiled<ND, H1D><<<cdiv(N, 64), 256, 0, sb>>>(x, W1, h1p, a_src1, a_dst1, N);
    counts_kernel<<<cdiv(N, 256), 256, 0, sb>>>(batch, N);
    if (fork) cudaEventRecord(evA, sb);

    // main: CSR build
    hist_kernel<<<cdiv(E, 256), 256, 0, 0>>>(ei, E);
    block_reduce_kernel<<<B, 256, 0, 0>>>(N);
    scan_fuse_kernel<<<B, 256, 0, 0>>>(B, N);
    scatter_kernel<<<cdiv(E, 256), 256, 0, 0>>>(ei, E);

    if (fork) cudaStreamWaitEvent(0, evA, 0);

    gat1_kernel<<<cdiv(N, 8), 256, 0, 0>>>(h1p, b1, y1p, N);
    gemm_tiled<H1D, H2D><<<cdiv(N, 64), 256, 0, 0>>>(y1p, W2, h2p, a_src2, a_dst2, N);
    gat2_kernel<<<cdiv(N, 8), 256, 0, 0>>>(h2p, b2, batch, N);

    fc_kernel<<<NG, 64, 0, 0>>>(Wfc, bfc, out);
}